// round 15
// baseline (speedup 1.0000x reference)
#include <cuda_runtime.h>
#include <math.h>

#define B_    4
#define N_    8192
#define D_    64
#define S_    1024
#define K_    32
#define CIN_  134
#define HID_  128
#define COUT_ 256
#define C8_   32
#define P_    131072   // B_*S_*K_
#define CTOT_ 518
#define NEG_INF_ (-3.402823466e38f)
#define CS_   (COUT_*S_)
#define NBLK_ 1024     // conv GEMM grid.x (P_/128)

// ---------------- scratch (device globals; no allocations allowed) --------
__device__ float g_Y [(size_t)CTOT_ * P_];
__device__ float g_Xs[(size_t)COUT_ * P_];
__device__ float g_Wt[300000];
__device__ float4 g_prm[CTOT_];
__device__ float g_feat[B_*COUT_*S_];
__device__ float g_q[B_*C8_*S_];
__device__ float g_k[B_*C8_*S_];
__device__ float g_v[B_*COUT_*S_];
__device__ float g_E [(size_t)B_*S_*S_];
__device__ float g_Ec[B_*COUT_*COUT_];
__device__ float g_Ecp[4*B_*COUT_*COUT_];
__device__ float g_opp[(size_t)4*B_*CS_];
__device__ float g_ocp[(size_t)4*B_*CS_];
__device__ float g_sp1[COUT_*NBLK_];       // per-(channel, nblk) sum partials
__device__ float g_sp2[COUT_*NBLK_];       // per-(channel, nblk) sumsq partials
__device__ float g_mean[COUT_];
__device__ float g_istd[COUT_];
__device__ int   g_fps [B_*S_];
__device__ float g_nxyz[B_*S_*3];
__device__ int   g_ball[B_*S_*K_];

// ---------------- FPS (redux.sync argmax, one barrier per iteration) --------
__global__ void fps_kernel(const float* __restrict__ xyz, float* __restrict__ outxyz)
{
    int b = blockIdx.x;
    const float* X = xyz + (size_t)b * N_ * 3;
    int tid = threadIdx.x;                 // 1024 threads
    int lane = tid & 31, wid = tid >> 5;
    float px[8], py[8], pz[8], dist[8];
#pragma unroll
    for (int i = 0; i < 8; i++){
        int j = tid + i * 1024;
        px[i] = X[j*3+0]; py[i] = X[j*3+1]; pz[i] = X[j*3+2];
        dist[i] = 1e10f;
    }
    __shared__ unsigned s_v[2][32];
    __shared__ unsigned s_i[2][32];
    float cx = X[0], cy = X[1], cz = X[2];
    int   far = 0;
    int   p = 0;

    for (int t = 0; t < S_; t++){
        if (tid == 0){
            g_fps[b*S_ + t] = far;
            g_nxyz[(b*S_+t)*3+0] = cx;
            g_nxyz[(b*S_+t)*3+1] = cy;
            g_nxyz[(b*S_+t)*3+2] = cz;
            outxyz[(b*S_+t)*3+0] = cx;
            outxyz[(b*S_+t)*3+1] = cy;
            outxyz[(b*S_+t)*3+2] = cz;
        }
        float bv = -1.0f; int bi = 0;
#pragma unroll
        for (int i = 0; i < 8; i++){
            float dx = px[i]-cx, dy = py[i]-cy, dz = pz[i]-cz;
            float d = fmaf(dz, dz, fmaf(dy, dy, dx*dx));
            float nd = fminf(dist[i], d);
            dist[i] = nd;
            if (nd > bv){ bv = nd; bi = tid + i*1024; }
        }
        unsigned vb = __float_as_uint(bv);
        unsigned mx = __reduce_max_sync(0xffffffffu, vb);
        unsigned im = (vb == mx) ? (unsigned)bi : 0xFFFFFFFFu;
        unsigned mn = __reduce_min_sync(0xffffffffu, im);
        if (lane == 0){ s_v[p][wid] = mx; s_i[p][wid] = mn; }
        __syncthreads();
        vb = s_v[p][lane];
        unsigned ib = s_i[p][lane];
        mx = __reduce_max_sync(0xffffffffu, vb);
        im = (vb == mx) ? ib : 0xFFFFFFFFu;
        mn = __reduce_min_sync(0xffffffffu, im);
        far = (int)mn;
        cx = X[far*3+0]; cy = X[far*3+1]; cz = X[far*3+2];
        p ^= 1;
    }
}

// ------ ball query (blocks <512) + weight transpose / prm init (rest) -------
__global__ void ball_prep(const float* __restrict__ xyz,
                          const float* __restrict__ W0, const float* __restrict__ W1,
                          const float* __restrict__ W2, const float* __restrict__ W3)
{
    if (blockIdx.x >= 512){
        int i = (blockIdx.x - 512) * 256 + threadIdx.x;
        if (i < CTOT_) g_prm[i] = make_float4(0.f, 1.f, 0.f, NEG_INF_);
        const int   Ms[4] = {HID_, HID_, HID_, COUT_};
        const int   Ks[4] = {CIN_, CIN_+HID_, CIN_+2*HID_, CIN_+3*HID_};
        const float* Ws[4] = {W0, W1, W2, W3};
        long off = 0;
#pragma unroll
        for (int l = 0; l < 4; l++){
            int n = Ms[l]*Ks[l];
            if (i >= 0 && i < n){
                int m = i / Ks[l], k = i - m*Ks[l];
                g_Wt[off + (long)k*Ms[l] + m] = Ws[l][i];
            }
            i -= n;
            off += n;
        }
        return;
    }
    int gw   = (blockIdx.x * blockDim.x + threadIdx.x) >> 5;
    int lane = threadIdx.x & 31;
    int b = gw >> 10;
    const float* X = xyz + (size_t)b * N_ * 3;
    float cx = g_nxyz[gw*3+0], cy = g_nxyz[gw*3+1], cz = g_nxyz[gw*3+2];
    float cn2 = __fadd_rn(__fadd_rn(__fmul_rn(cx,cx), __fmul_rn(cy,cy)), __fmul_rn(cz,cz));
    int* out = g_ball + gw * K_;
    int cnt = 0;
    for (int base = 0; base < N_ && cnt < K_; base += 256){
        float xx[8], yy[8], zz[8];
#pragma unroll
        for (int i = 0; i < 8; i++){
            int j = base + i*32 + lane;
            xx[i] = X[j*3+0]; yy[i] = X[j*3+1]; zz[i] = X[j*3+2];
        }
        float d[8];
#pragma unroll
        for (int i = 0; i < 8; i++){
            float pn2 = __fadd_rn(__fadd_rn(__fmul_rn(xx[i],xx[i]), __fmul_rn(yy[i],yy[i])),
                                  __fmul_rn(zz[i],zz[i]));
            float dt  = fmaf(cz, zz[i], fmaf(cy, yy[i], __fmul_rn(cx, xx[i])));
            d[i] = __fsub_rn(__fadd_rn(cn2, pn2), __fmul_rn(2.0f, dt));
        }
#pragma unroll
        for (int i = 0; i < 8; i++){
            bool inb = !(d[i] > 0.04f);
            unsigned msk = __ballot_sync(0xffffffffu, inb);
            int pos = cnt + __popc(msk & ((1u << lane) - 1u));
            if (inb && pos < K_) out[pos] = base + i*32 + lane;
            cnt += __popc(msk);
        }
    }
    __syncwarp();
    if (cnt < K_){
        int first = out[0];
        for (int pq = cnt + lane; pq < K_; pq += 32) out[pq] = first;
    }
}

// ---------------- build x0 into g_Y channels [0,134) ------------------------
__global__ void build_x0(const float* __restrict__ xyz, const float* __restrict__ pts)
{
    int bs  = blockIdx.x;
    int b   = bs >> 10;
    int tid = threadIdx.x;                  // 256
    __shared__ int   sj[32];
    __shared__ float sgx[32], sgy[32], sgz[32];
    __shared__ float scp[64];
    __shared__ float scen[3];
    if (tid < 32){
        int j = g_ball[bs*K_ + tid]; sj[tid] = j;
        const float* Xp = xyz + ((size_t)b*N_ + j)*3;
        sgx[tid] = Xp[0]; sgy[tid] = Xp[1]; sgz[tid] = Xp[2];
    } else if (tid < 96){
        scp[tid-32] = pts[((size_t)b*N_ + g_fps[bs])*D_ + (tid-32)];
    } else if (tid < 99){
        scen[tid-96] = g_nxyz[bs*3 + (tid-96)];
    }
    __syncthreads();
    const float* Pb = pts + (size_t)b * N_ * D_;
    size_t pbase = (size_t)bs * K_;
    for (int idx = tid; idx < CIN_ * K_; idx += 256){
        int c = idx >> 5, k = idx & 31;
        int j = sj[k];
        float val;
        if (c < 3){
            float g = (c==0) ? sgx[k] : (c==1) ? sgy[k] : sgz[k];
            float cc = scen[c];
            val = (g - cc) - cc;
        } else if (c < 67){
            val = Pb[(size_t)j*D_ + (c-3)] - scp[c-3];
        } else if (c < 70){
            int c3 = c - 67;
            float g = (c3==0) ? sgx[k] : (c3==1) ? sgy[k] : sgz[k];
            val = g - scen[c3];
        } else {
            val = Pb[(size_t)j*D_ + (c-70)];
        }
        g_Y[(size_t)c*P_ + pbase + k] = val;
    }
}

// ---------------- tf32 helpers ------------------------------------------------
__device__ __forceinline__ unsigned hi_tf(float x){
    return __float_as_uint(x) & 0xFFFFE000u;
}
__device__ __forceinline__ void mma_tf32(float* d, const unsigned* a, const unsigned* b){
    asm volatile(
        "mma.sync.aligned.m16n8k8.row.col.f32.tf32.tf32.f32 "
        "{%0,%1,%2,%3}, {%4,%5,%6,%7}, {%8,%9}, {%0,%1,%2,%3};"
        : "+f"(d[0]), "+f"(d[1]), "+f"(d[2]), "+f"(d[3])
        : "r"(a[0]), "r"(a[1]), "r"(a[2]), "r"(a[3]), "r"(b[0]), "r"(b[1]));
}

#define SMP_ 136

#define TC_COMPUTE(AS, BS)                                                    \
    {                                                                         \
        unsigned ah[16], al[16], bh[8], bl[8];                                \
        _Pragma("unroll")                                                     \
        for (int mt = 0; mt < 4; mt++){                                       \
            int mb = wm + mt*16 + g;                                          \
            float x0 = AS[tig  ][mb];                                         \
            float x1 = AS[tig  ][mb+8];                                       \
            float x2 = AS[tig+4][mb];                                         \
            float x3 = AS[tig+4][mb+8];                                       \
            unsigned h;                                                       \
            h = hi_tf(x0); ah[mt*4+0] = h; al[mt*4+0] = __float_as_uint(x0 - __uint_as_float(h)); \
            h = hi_tf(x1); ah[mt*4+1] = h; al[mt*4+1] = __float_as_uint(x1 - __uint_as_float(h)); \
            h = hi_tf(x2); ah[mt*4+2] = h; al[mt*4+2] = __float_as_uint(x2 - __uint_as_float(h)); \
            h = hi_tf(x3); ah[mt*4+3] = h; al[mt*4+3] = __float_as_uint(x3 - __uint_as_float(h)); \
        }                                                                     \
        _Pragma("unroll")                                                     \
        for (int nt = 0; nt < 4; nt++){                                       \
            int nb = wn + nt*8 + g;                                           \
            float y0 = BS[tig  ][nb];                                         \
            float y1 = BS[tig+4][nb];                                         \
            unsigned h;                                                       \
            h = hi_tf(y0); bh[nt*2+0] = h; bl[nt*2+0] = __float_as_uint(y0 - __uint_as_float(h)); \
            h = hi_tf(y1); bh[nt*2+1] = h; bl[nt*2+1] = __float_as_uint(y1 - __uint_as_float(h)); \
        }                                                                     \
        _Pragma("unroll")                                                     \
        for (int mt = 0; mt < 4; mt++)                                        \
            _Pragma("unroll")                                                 \
            for (int nt = 0; nt < 4; nt++)                                    \
                mma_tf32(acc[mt][nt], ah + mt*4, bh + nt*2);                  \
        _Pragma("unroll")                                                     \
        for (int mt = 0; mt < 4; mt++)                                        \
            _Pragma("unroll")                                                 \
            for (int nt = 0; nt < 4; nt++)                                    \
                mma_tf32(acc[mt][nt], ah + mt*4, bl + nt*2);                  \
        _Pragma("unroll")                                                     \
        for (int mt = 0; mt < 4; mt++)                                        \
            _Pragma("unroll")                                                 \
            for (int nt = 0; nt < 4; nt++)                                    \
                mma_tf32(acc[mt][nt], al + mt*4, bh + nt*2);                  \
    }

// ------- 3xTF32 conv GEMM, k-tile 16, fused BN-stat partials -----------------
// C[m][n] = sum_k At[k*M+m]*f(B[k*Nn+n]); also emits per-(channel, nblk)
// sum / sumsq partials of C into g_sp1/g_sp2. Nn == P_, grid.x == NBLK_.
__global__ void __launch_bounds__(256, 2)
gemm_tc(const float* __restrict__ At, const float* __restrict__ Bm,
        float* __restrict__ C, const float4* __restrict__ prm,
        int M, int Nn, int Kk)
{
    __shared__ float As[2][16][SMP_];
    __shared__ float Bs[2][16][SMP_];
    __shared__ float ssum[2][4][64], sssq[2][4][64];
    int tid = threadIdx.x, lane = tid & 31, wid = tid >> 5;
    int n0 = blockIdx.x * 128, m0 = blockIdx.y * 128;
    int c4 = lane << 2;
    int wm = (wid >> 2) * 64;
    int wn = (wid & 3) * 32;
    int g = lane >> 2, tig = lane & 3;
    int ntiles = (Kk + 15) >> 4;

    const float4 z4 = make_float4(0.f,0.f,0.f,0.f);

    // load tile 0 (rows wid and wid+8)
#pragma unroll
    for (int hrow = 0; hrow < 2; hrow++){
        int kg = wid + hrow*8;
        float4 av = z4, bv = z4;
        if (kg < Kk){
            av = *(const float4*)(At + (long)kg*M  + m0 + c4);
            bv = *(const float4*)(Bm + (long)kg*Nn + n0 + c4);
            float4 pp = prm[kg];
            bv.x = fmaxf((bv.x - pp.x)*pp.y + pp.z, pp.w);
            bv.y = fmaxf((bv.y - pp.x)*pp.y + pp.z, pp.w);
            bv.z = fmaxf((bv.z - pp.x)*pp.y + pp.z, pp.w);
            bv.w = fmaxf((bv.w - pp.x)*pp.y + pp.z, pp.w);
        }
        *(float4*)&As[0][wid + hrow*8][c4] = av;
        *(float4*)&Bs[0][wid + hrow*8][c4] = bv;
    }
    __syncthreads();

    float acc[4][4][4];
#pragma unroll
    for (int mt = 0; mt < 4; mt++)
#pragma unroll
        for (int nt = 0; nt < 4; nt++)
#pragma unroll
            for (int r = 0; r < 4; r++) acc[mt][nt][r] = 0.f;

    int buf = 0;
    for (int t = 1; t <= ntiles; t++){
        float4 av0 = z4, bv0 = z4, av1 = z4, bv1 = z4;
        bool have = (t < ntiles);
        if (have){
            int kg0 = t*16 + wid, kg1 = kg0 + 8;
            if (kg0 < Kk){
                av0 = *(const float4*)(At + (long)kg0*M  + m0 + c4);
                bv0 = *(const float4*)(Bm + (long)kg0*Nn + n0 + c4);
                float4 pp = prm[kg0];
                bv0.x = fmaxf((bv0.x - pp.x)*pp.y + pp.z, pp.w);
                bv0.y = fmaxf((bv0.y - pp.x)*pp.y + pp.z, pp.w);
                bv0.z = fmaxf((bv0.z - pp.x)*pp.y + pp.z, pp.w);
                bv0.w = fmaxf((bv0.w - pp.x)*pp.y + pp.z, pp.w);
            }
            if (kg1 < Kk){
                av1 = *(const float4*)(At + (long)kg1*M  + m0 + c4);
                bv1 = *(const float4*)(Bm + (long)kg1*Nn + n0 + c4);
                float4 pp = prm[kg1];
                bv1.x = fmaxf((bv1.x - pp.x)*pp.y + pp.z, pp.w);
                bv1.y = fmaxf((bv1.y - pp.x)*pp.y + pp.z, pp.w);
                bv1.z = fmaxf((bv1.z - pp.x)*pp.y + pp.z, pp.w);
                bv1.w = fmaxf((bv1.w - pp.x)*pp.y + pp.z, pp.w);
            }
        }
        // compute both 8-deep sub-tiles of current buffer
        TC_COMPUTE((As[buf]    ), (Bs[buf]    ));
        TC_COMPUTE((As[buf] + 8), (Bs[buf] + 8));
        if (have){
            int nb = buf ^ 1;
            *(float4*)&As[nb][wid    ][c4] = av0;
            *(float4*)&Bs[nb][wid    ][c4] = bv0;
            *(float4*)&As[nb][wid + 8][c4] = av1;
            *(float4*)&Bs[nb][wid + 8][c4] = bv1;
            __syncthreads();
            buf ^= 1;
        }
    }

    // ---- epilogue: C writes + per-channel stat partials ----
#pragma unroll
    for (int mt = 0; mt < 4; mt++){
        int r0 = m0 + wm + mt*16 + g;
        int r1 = r0 + 8;
#pragma unroll
        for (int nt = 0; nt < 4; nt++){
            int cc = n0 + wn + nt*8 + tig*2;
            *(float2*)&C[(long)r0*Nn + cc] = make_float2(acc[mt][nt][0], acc[mt][nt][1]);
            *(float2*)&C[(long)r1*Nn + cc] = make_float2(acc[mt][nt][2], acc[mt][nt][3]);
        }
        // row sums / sumsq over this warp's 8 columns
        float s0 = 0.f, s1 = 0.f, q0 = 0.f, q1 = 0.f;
#pragma unroll
        for (int nt = 0; nt < 4; nt++){
            s0 += acc[mt][nt][0] + acc[mt][nt][1];
            s1 += acc[mt][nt][2] + acc[mt][nt][3];
            q0 = fmaf(acc[mt][nt][0], acc[mt][nt][0], q0);
            q0 = fmaf(acc[mt][nt][1], acc[mt][nt][1], q0);
            q1 = fmaf(acc[mt][nt][2], acc[mt][nt][2], q1);
            q1 = fmaf(acc[mt][nt][3], acc[mt][nt][3], q1);
        }
        // reduce over tig (4 lanes)
        s0 += __shfl_xor_sync(0xffffffffu, s0, 1);
        s0 += __shfl_xor_sync(0xffffffffu, s0, 2);
        s1 += __shfl_xor_sync(0xffffffffu, s1, 1);
        s1 += __shfl_xor_sync(0xffffffffu, s1, 2);
        q0 += __shfl_xor_sync(0xffffffffu, q0, 1);
        q0 += __shfl_xor_sync(0xffffffffu, q0, 2);
        q1 += __shfl_xor_sync(0xffffffffu, q1, 1);
        q1 += __shfl_xor_sync(0xffffffffu, q1, 2);
        if (tig == 0){
            int half = wm >> 6, ws = wn >> 5;
            ssum[half][ws][mt*16 + g]     = s0;
            ssum[half][ws][mt*16 + g + 8] = s1;
            sssq[half][ws][mt*16 + g]     = q0;
            sssq[half][ws][mt*16 + g + 8] = q1;
        }
    }
    __syncthreads();
    if (tid < 128){
        int half = tid >> 6, lr = tid & 63;
        float s = (ssum[half][0][lr] + ssum[half][1][lr])
                + (ssum[half][2][lr] + ssum[half][3][lr]);
        float qq = (sssq[half][0][lr] + sssq[half][1][lr])
                 + (sssq[half][2][lr] + sssq[half][3][lr]);
        int ch = m0 + tid;
        g_sp1[(long)ch*NBLK_ + blockIdx.x] = s;
        g_sp2[(long)ch*NBLK_ + blockIdx.x] = qq;
    }
}

// ---- reduce stat partials (fixed order, f64) + publish BN params ------------
__global__ void bn_reduce(int coff, const float* __restrict__ gg,
                          const float* __restrict__ be)
{
    int c = blockIdx.x;
    int tid = threadIdx.x;
    double s = 0.0, ss = 0.0;
    for (int j = tid; j < NBLK_; j += 256){
        s  += (double)g_sp1[(long)c*NBLK_ + j];
        ss += (double)g_sp2[(long)c*NBLK_ + j];
    }
    __shared__ double sh0[256], sh1[256];
    sh0[tid] = s; sh1[tid] = ss; __syncthreads();
    for (int off = 128; off; off >>= 1){
        if (tid < off){ sh0[tid] += sh0[tid+off]; sh1[tid] += sh1[tid+off]; }
        __syncthreads();
    }
    if (tid == 0){
        double m   = sh0[0] / (double)P_;
        double var = sh1[0] / (double)P_ - m*m;
        float mf = (float)m;
        float isf = (float)(1.0 / sqrt(var + 1e-5));
        g_mean[c] = mf;
        g_istd[c] = isf;
        if (coff >= 0)
            g_prm[coff + c] = make_float4(mf, isf * gg[c], be[c], 0.f);
    }
}

// ------- 3xTF32 GEMM with K-split: A row-major; B row-major or K-major -------
__global__ void __launch_bounds__(256)
gemm_tc2s(const float* __restrict__ A, const float* __restrict__ Bm,
          float* __restrict__ Cp,
          int M, int Nn, int Kk, int lda, int ldb, int bRow, int NC,
          long sA, long sB)
{
    int z = blockIdx.z;
    int b = z / NC, kc = z - b*NC;
    A  += (long)b * sA + (long)kc * Kk;
    Bm += (long)b * sB + (bRow ? (long)kc * Kk : (long)kc * Kk * Nn);
    float* C = Cp + (long)z * M * Nn;
    __shared__ float As[2][8][SMP_];
    __shared__ float Bs[2][8][SMP_];
    int tid = threadIdx.x, lane = tid & 31, wid = tid >> 5;
    int n0 = blockIdx.x * 128, m0 = blockIdx.y * 128;
    int mf = tid & 127, kq = (tid >> 7) << 2;
    int kr = wid, c4 = lane << 2;
    int wm = (wid >> 2) * 64;
    int wn = (wid & 3) * 32;
    int g = lane >> 2, tig = lane & 3;
    int ntiles = Kk >> 3;

    {
        float4 av = *(const float4*)(A + (long)(m0+mf)*lda + kq);
#pragma unroll
        for (int i = 0; i < 4; i++) As[0][kq+i][mf] = ((float*)&av)[i];
        if (bRow){
            float4 bv = *(const float4*)(Bm + (long)(n0+mf)*ldb + kq);
#pragma unroll
            for (int i = 0; i < 4; i++) Bs[0][kq+i][mf] = ((float*)&bv)[i];
        } else {
            float4 bv = *(const float4*)(Bm + (long)kr*Nn + n0 + c4);
            *(float4*)&Bs[0][kr][c4] = bv;
        }
    }
    __syncthreads();

    float acc[4][4][4];
#pragma unroll
    for (int mt = 0; mt < 4; mt++)
#pragma unroll
        for (int nt = 0; nt < 4; nt++)
#pragma unroll
            for (int r = 0; r < 4; r++) acc[mt][nt][r] = 0.f;

    int buf = 0;
    for (int t = 1; t <= ntiles; t++){
        float4 av, bv;
        bool have = (t < ntiles);
        if (have){
            int k0 = t*8;
            av = *(const float4*)(A + (long)(m0+mf)*lda + k0 + kq);
            if (bRow) bv = *(const float4*)(Bm + (long)(n0+mf)*ldb + k0 + kq);
            else      bv = *(const float4*)(Bm + (long)(k0+kr)*Nn + n0 + c4);
        }
        TC_COMPUTE(As[buf], Bs[buf]);
        if (have){
            int nb = buf ^ 1;
#pragma unroll
            for (int i = 0; i < 4; i++) As[nb][kq+i][mf] = ((float*)&av)[i];
            if (bRow){
#pragma unroll
                for (int i = 0; i < 4; i++) Bs[nb][kq+i][mf] = ((float*)&bv)[i];
            } else {
                *(float4*)&Bs[nb][kr][c4] = bv;
            }
            __syncthreads();
            buf ^= 1;
        }
    }

#pragma unroll
    for (int mt = 0; mt < 4; mt++){
        int r0 = m0 + wm + mt*16 + g;
        int r1 = r0 + 8;
#pragma unroll
        for (int nt = 0; nt < 4; nt++){
            int cc = n0 + wn + nt*8 + tig*2;
            *(float2*)&C[(long)r0*Nn + cc] = make_float2(acc[mt][nt][0], acc[mt][nt][1]);
            *(float2*)&C[(long)r1*Nn + cc] = make_float2(acc[mt][nt][2], acc[mt][nt][3]);
        }
    }
}

// ---------------- fused q/k projection (64x64 tile) --------------------------
__global__ void gemm_qk(const float* __restrict__ Wq, const float* __restrict__ Wk,
                        const float* __restrict__ bq, const float* __restrict__ bk,
                        const float* __restrict__ feat,
                        float* __restrict__ qout, float* __restrict__ kout)
{
    int z = blockIdx.z, b = z >> 1, sel = z & 1;
    const float* A    = sel ? Wk : Wq;
    const float* bias = sel ? bk : bq;
    const float* Bm = feat + (long)b*CS_;
    float* C = (sel ? kout : qout) + (long)b*C8_*S_;
    const int M = C8_, Nn = S_, Kk = COUT_;
    __shared__ float As[16][68];
    __shared__ float Bs[16][64];
    int tid = threadIdx.x;
    int m0 = 0, n0 = blockIdx.x * 64;
    int ty = tid >> 4, tx = tid & 15;
    float acc[4][4] = {};
    for (int k0 = 0; k0 < Kk; k0 += 16){
#pragma unroll
        for (int i = tid; i < 1024; i += 256){
            int rr = i >> 4, cc = i & 15;
            int mm = m0 + rr, kk = k0 + cc;
            As[cc][rr] = (mm < M) ? A[(long)mm*Kk + kk] : 0.f;
        }
#pragma unroll
        for (int i = tid; i < 1024; i += 256){
            int rr = i >> 6, cc = i & 63;
            int kk = k0 + rr;
            Bs[rr][cc] = Bm[(long)kk*Nn + n0 + cc];
        }
        __syncthreads();
#pragma unroll
        for (int kk = 0; kk < 16; kk++){
            float4 a  = *(const float4*)&As[kk][ty*4];
            float4 bv = *(const float4*)&Bs[kk][tx*4];
            float av[4] = {a.x, a.y, a.z, a.w};
            float bb[4] = {bv.x, bv.y, bv.z, bv.w};
#pragma unroll
            for (int i = 0; i < 4; i++)
#pragma unroll
                for (int j = 0; j < 4; j++)
                    acc[i][j] = fmaf(av[i], bb[j], acc[i][j]);
        }
        __syncthreads();
    }
#pragma unroll
    for (int i = 0; i < 4; i++){
        int mm = m0 + ty*4 + i;
        if (mm < M){
            float bsv = bias[mm];
            float4 o = make_float4(acc[i][0]+bsv, acc[i][1]+bsv, acc[i][2]+bsv, acc[i][3]+bsv);
            *(float4*)&C[(long)mm*Nn + n0 + tx*4] = o;
        }
    }
}

// ---------------- small GEMMs (64x64 tile) -----------------------------------
__global__ void gemm_nn(const float* __restrict__ A, const float* __restrict__ Bm,
                        float* __restrict__ C, const float* __restrict__ bias,
                        int M, int Nn, int Kk, long sA, long sB, long sC)
{
    A  += (long)blockIdx.z * sA;
    Bm += (long)blockIdx.z * sB;
    C  += (long)blockIdx.z * sC;
    __shared__ float As[16][68];
    __shared__ float Bs[16][64];
    int tid = threadIdx.x;
    int m0 = blockIdx.y * 64, n0 = blockIdx.x * 64;
    int ty = tid >> 4, tx = tid & 15;
    float acc[4][4] = {};
    for (int k0 = 0; k0 < Kk; k0 += 16){
#pragma unroll
        for (int i = tid; i < 1024; i += 256){
            int rr = i >> 4, cc = i & 15;
            int mm = m0 + rr, kk = k0 + cc;
            As[cc][rr] = (mm < M && kk < Kk) ? A[(long)mm*Kk + kk] : 0.f;
        }
#pragma unroll
        for (int i = tid; i < 1024; i += 256){
            int rr = i >> 6, cc = i & 63;
            int kk = k0 + rr;
            Bs[rr][cc] = (kk < Kk) ? Bm[(long)kk*Nn + n0 + cc] : 0.f;
        }
        __syncthreads();
#pragma unroll
        for (int kk = 0; kk < 16; kk++){
            float4 a  = *(const float4*)&As[kk][ty*4];
            float4 bv = *(const float4*)&Bs[kk][tx*4];
            float av[4] = {a.x, a.y, a.z, a.w};
            float bb[4] = {bv.x, bv.y, bv.z, bv.w};
#pragma unroll
            for (int i = 0; i < 4; i++)
#pragma unroll
                for (int j = 0; j < 4; j++)
                    acc[i][j] = fmaf(av[i], bb[j], acc[i][j]);
        }
        __syncthreads();
    }
#pragma unroll
    for (int i = 0; i < 4; i++){
        int mm = m0 + ty*4 + i;
        if (mm < M){
            float bsv = bias ? bias[mm] : 0.f;
            float4 o = make_float4(acc[i][0]+bsv, acc[i][1]+bsv, acc[i][2]+bsv, acc[i][3]+bsv);
            *(float4*)&C[(long)mm*Nn + n0 + tx*4] = o;
        }
    }
}

__global__ void gemm_tn(const float* __restrict__ A, const float* __restrict__ Bm,
                        float* __restrict__ C,
                        int M, int Nn, int Kk, int lda, int ldb,
                        long sA, long sB, long sC)
{
    A += (long)blockIdx.z*sA; Bm += (long)blockIdx.z*sB; C += (long)blockIdx.z*sC;
    __shared__ float As[16][64], Bs[16][64];
    int tid = threadIdx.x;
    int m0 = blockIdx.y * 64, n0 = blockIdx.x * 64;
    int ty = tid >> 4, tx = tid & 15;
    float acc[4][4] = {};
    for (int k0 = 0; k0 < Kk; k0 += 16){
#pragma unroll
        for (int i = tid; i < 1024; i += 256){
            int rr = i >> 6, cc = i & 63;
            int kk = k0 + rr;
            As[rr][cc] = (kk < Kk) ? A[(long)kk*lda + m0 + cc] : 0.f;
            Bs[rr][cc] = (kk < Kk) ? Bm[(long)kk*ldb + n0 + cc] : 0.f;
        }
        __syncthreads();
#pragma unroll
        for (int kk = 0; kk < 16; kk++){
            float4 a  = *(const float4*)&As[kk][ty*4];
            float4 bv = *(const float4*)&Bs[kk][tx*4];
            float av[4] = {a.x, a.y, a.z, a.w};
            float bb[4] = {bv.x, bv.y, bv.z, bv.w};
#pragma unroll
            for (int i = 0; i < 4; i++)
#pragma unroll
                for (int j = 0; j < 4; j++)
                    acc[i][j] = fmaf(av[i], bb[j], acc[i][j]);
        }
        __syncthreads();
    }
#pragma unroll
    for (int i = 0; i < 4; i++){
        int mm = m0 + ty*4 + i;
        float4 o = make_float4(acc[i][0], acc[i][1], acc[i][2], acc[i][3]);
        *(float4*)&C[(long)mm*Nn + n0 + tx*4] = o;
    }
}

// ---- K-split Kahan NT GEMM for energy_c -------------------------------------
__global__ void ec_kah_split(const float* __restrict__ feat, float* __restrict__ Ecp)
{
    int z = blockIdx.z;
    int b = z >> 2, kc = z & 3;
    const float* A = feat + (long)b*CS_ + kc*256;
    float* C = Ecp + ((long)kc*B_ + b) * COUT_*COUT_;
    __shared__ float As[16][68], Bs[16][68];
    int tid = threadIdx.x;
    int m0 = blockIdx.y * 64, n0 = blockIdx.x * 64;
    int ty = tid >> 4, tx = tid & 15;
    float acc[4][4] = {};
    float cmp[4][4] = {};
    for (int k0 = 0; k0 < 256; k0 += 16){
#pragma unroll
        for (int i = tid; i < 1024; i += 256){
            int mm = i >> 4, kd = i & 15;
            int kk = k0 + kd;
            As[kd][mm] = A[(long)(m0+mm)*S_ + kk];
            Bs[kd][mm] = A[(long)(n0+mm)*S_ + kk];
        }
        __syncthreads();
#pragma unroll
        for (int kk = 0; kk < 16; kk++){
            float4 a  = *(const float4*)&As[kk][ty*4];
            float4 bv = *(const float4*)&Bs[kk][tx*4];
            float av[4] = {a.x, a.y, a.z, a.w};
            float bb[4] = {bv.x, bv.y, bv.z, bv.w};
#pragma unroll
            for (int i = 0; i < 4; i++)
#pragma unroll
                for (int j = 0; j < 4; j++){
                    float y = fmaf(av[i], bb[j], -cmp[i][j]);
                    float t = acc[i][j] + y;
                    cmp[i][j] = (t - acc[i][j]) - y;
                    acc[i][j] = t;
                }
        }
        __syncthreads();
    }
#pragma unroll
    for (int i = 0; i < 4; i++){
        int mm = m0 + ty*4 + i;
        float4 o = make_float4(acc[i][0], acc[i][1], acc[i][2], acc[i][3]);
        *(float4*)&C[(long)mm*COUT_ + n0 + tx*4] = o;
    }
}

// ------- fused layer-4 BN + ReLU + max over K --------------------------------
__global__ void bn_relu_maxk(const float* __restrict__ Xs,
                             const float* __restrict__ gg, const float* __restrict__ be)
{
    int i = blockIdx.x * 256 + threadIdx.x;
    int s = i & 1023, c = (i >> 10) & 255, b = i >> 18;
    float m = g_mean[c], is = g_istd[c], gv = gg[c], bb = be[c];
    float sc = is * gv;
    const float4* src = (const float4*)(Xs + (size_t)c * P_ + ((size_t)(b*S_ + s)) * K_);
    float best = 0.f;
#pragma unroll
    for (int k = 0; k < 8; k++){
        float4 v = src[k];
        best = fmaxf(best, (v.x - m)*sc + bb);
        best = fmaxf(best, (v.y - m)*sc + bb);
        best = fmaxf(best, (v.z - m)*sc + bb);
        best = fmaxf(best, (v.w - m)*sc + bb);
    }
    g_feat[i] = best;
}

// ---------------- softmaxes ---------------------------------------------------
__global__ void softmax_rows_1024(float* __restrict__ E)
{
    int row = blockIdx.x;
    float* e = E + (size_t)row * 1024;
    int tid = threadIdx.x;
    __shared__ float sh[256];
    float mx = -3.402823466e38f;
    for (int c = tid; c < 1024; c += 256) mx = fmaxf(mx, e[c]);
    sh[tid] = mx; __syncthreads();
    for (int off = 128; off; off >>= 1){ if (tid < off) sh[tid] = fmaxf(sh[tid], sh[tid+off]); __syncthreads(); }
    mx = sh[0]; __syncthreads();
    float sum = 0.f;
    float vals[4];
#pragma unroll
    for (int q = 0; q < 4; q++){
        int c = tid + q*256;
        float v = expf(e[c] - mx);
        vals[q] = v; sum += v;
    }
    sh[tid] = sum; __syncthreads();
    for (int off = 128; off; off >>= 1){ if (tid < off) sh[tid] += sh[tid+off]; __syncthreads(); }
    float inv = 1.0f / sh[0];
#pragma unroll
    for (int q = 0; q < 4; q++) e[tid + q*256] = vals[q] * inv;
}

// channel softmax fused with partial combine (fixed f64 order)
__global__ void softmax_c_kernel(const float* __restrict__ Ecp, float* __restrict__ Ecout)
{
    int row = blockIdx.x;
    int i = row * 256 + threadIdx.x;
    const long NB = (long)B_*COUT_*COUT_;
    int tid = threadIdx.x;
    __shared__ double sh[256];
    double v = ((double)Ecp[i] + (double)Ecp[i + NB])
             + ((double)Ecp[i + 2*NB] + (double)Ecp[i + 3*NB]);
    v = (double)(float)v;
    sh[tid] = v; __syncthreads();
    for (int off = 128; off; off >>= 1){ if (tid < off) sh[tid] = fmax(sh[tid], sh[tid+off]); __syncthreads(); }
    double m1 = sh[0]; __syncthreads();
    double t = m1 - v;
    sh[tid] = t; __syncthreads();
    for (int off = 128; off; off >>= 1){ if (tid < off) sh[tid] = fmax(sh[tid], sh[tid+off]); __syncthreads(); }
    double mt = sh[0]; __syncthreads();
    double ex = exp(t - mt);
    sh[tid] = ex; __syncthreads();
    for (int off = 128; off; off >>= 1){ if (tid < off) sh[tid] += sh[tid+off]; __syncthreads(); }
    Ecout[i] = (float)(ex / sh[0]);
}

// ---------------- finalize: combine K-chunk partials + compose output --------
__global__ void finalize_kernel(float* __restrict__ out, const float* __restrict__ gamma)
{
    int i = blockIdx.x * 256 + threadIdx.x;
    int c = i & 255, s = (i >> 8) & 1023, b = i >> 18;
    long f = ((long)(b*COUT_ + c)) * S_ + s;
    long r = (long)c * S_ + s;
    long zb = (long)b * 4;
    double sp = ((double)g_opp[(zb+0)*CS_ + r] + (double)g_opp[(zb+1)*CS_ + r])
              + ((double)g_opp[(zb+2)*CS_ + r] + (double)g_opp[(zb+3)*CS_ + r]);
    double sc = ((double)g_ocp[(zb+0)*CS_ + r] + (double)g_ocp[(zb+1)*CS_ + r])
              + ((double)g_ocp[(zb+2)*CS_ + r] + (double)g_ocp[(zb+3)*CS_ + r]);
    float outp = (float)sp, outc = (float)sc;
    float g = gamma[0];
    float val = g * (outp + outc) + 2.0f * g_feat[f];
    out[(size_t)B_*S_*3 + i] = val;
}

// ---------------- launch -------------------------------------------------------
extern "C" void kernel_launch(void* const* d_in, const int* in_sizes, int n_in,
                              void* d_out, int out_size)
{
    const float* xyz    = (const float*)d_in[0];
    const float* points = (const float*)d_in[1];
    const float* W[4]  = {(const float*)d_in[2],  (const float*)d_in[6],
                          (const float*)d_in[10], (const float*)d_in[14]};
    const float* gl[4] = {(const float*)d_in[4],  (const float*)d_in[8],
                          (const float*)d_in[12], (const float*)d_in[16]};
    const float* bel[4]= {(const float*)d_in[5],  (const float*)d_in[9],
                          (const float*)d_in[13], (const float*)d_in[17]};
    const float* Wq = (const float*)d_in[18]; const float* bq = (const float*)d_in[19];
    const float* Wk = (const float*)d_in[20]; const float* bk = (const float*)d_in[21];
    const float* Wv = (const float*)d_in[22]; const float* bv = (const float*)d_in[23];
    const float* gamma = (const float*)d_in[24];
    float* out = (float*)d_out;

    float *Y, *Xs, *Wt, *feat, *q, *k, *v, *E, *Ec, *Ecp, *opp, *ocp;
    float4* prm;
    cudaGetSymbolAddress((void**)&Y,    g_Y);
    cudaGetSymbolAddress((void**)&Xs,   g_Xs);
    cudaGetSymbolAddress((void**)&Wt,   g_Wt);
    cudaGetSymbolAddress((void**)&prm,  g_prm);
    cudaGetSymbolAddress((void**)&feat, g_feat);
    cudaGetSymbolAddress((void**)&q,    g_q);
    cudaGetSymbolAddress((void**)&k,    g_k);
    cudaGetSymbolAddress((void**)&v,    g_v);
    cudaGetSymbolAddress((void**)&E,    g_E);
    cudaGetSymbolAddress((void**)&Ec,   g_Ec);
    cudaGetSymbolAddress((void**)&Ecp,  g_Ecp);
    cudaGetSymbolAddress((void**)&opp,  g_opp);
    cudaGetSymbolAddress((void**)&ocp,  g_ocp);

    int   Kl[4]  = {CIN_, CIN_+HID_, CIN_+2*HID_, CIN_+3*HID_};
    int   COl[4] = {HID_, HID_, HID_, COUT_};
    long Woff[4];
    {
        long o = 0;
        for (int l = 0; l < 4; l++){ Woff[l] = o; o += (long)Kl[l]*COl[l]; }
    }

    // launch order: fps(1), ball_prep(2), build_x0(3), gemm_tc L1(4) <- profiled
    fps_kernel<<<B_, 1024>>>(xyz, out);
    ball_prep<<<512 + (233216 + 255)/256, 256>>>(xyz, W[0], W[1], W[2], W[3]);
    build_x0<<<B_*S_, 256>>>(xyz, points);

    // stage 3: DenseNet — 3xTF32 conv with fused BN-stat partials
    float* rawdst[4] = {Y + (size_t)CIN_*P_, Y + (size_t)(CIN_+HID_)*P_,
                        Y + (size_t)(CIN_+2*HID_)*P_, Xs};
    for (int l = 0; l < 4; l++){
        gemm_tc<<<dim3(NBLK_, COl[l]/128, 1), 256>>>(Wt + Woff[l], Y, rawdst[l],
                                                     prm, COl[l], P_, Kl[l]);
        bn_reduce<<<COl[l], 256>>>((l < 3) ? Kl[l] : -1, gl[l], bel[l]);
        if (l == 3)
            bn_relu_maxk<<<(B_*COUT_*S_)/256, 256>>>(Xs, gl[l], bel[l]);
    }

    // stage 5: dual attention
    long fS = (long)CS_;
    gemm_qk<<<dim3(S_/64, 1, 2*B_), 256>>>(Wq, Wk, bq, bk, feat, q, k);
    gemm_nn<<<dim3(S_/64, 4, B_), 256>>>(Wv, feat, v, bv, COUT_, S_, COUT_, 0, fS, fS);

    gemm_tn<<<dim3(S_/64, S_/64, B_), 256>>>(q, k, E, S_, S_, C8_, S_, S_,
                                             (long)C8_*S_, (long)C8_*S_, (long)S_*S_);
    softmax_rows_1024<<<B_*S_, 256>>>(E);
    gemm_tc2s<<<dim3(S_/128, COUT_/128, B_*4), 256>>>(v, E, opp,
                                                      COUT_, S_, 256, S_, S_, 1, 4,
                                                      fS, (long)S_*S_);

    // channel attention
    ec_kah_split<<<dim3(COUT_/64, COUT_/64, B_*4), 256>>>(feat, Ecp);
    softmax_c_kernel<<<B_*COUT_, 256>>>(Ecp, Ec);
    gemm_tc2s<<<dim3(S_/128, COUT_/128, B_*4), 256>>>(Ec, feat, ocp,
                                                      COUT_, S_, 64, COUT_, 0, 0, 4,
                                                      (long)COUT_*COUT_, fS);

    finalize_kernel<<<(B_*S_*COUT_)/256, 256>>>(out, gamma);
}

// round 16
// speedup vs baseline: 1.0676x; 1.0676x over previous
#include <cuda_runtime.h>
#include <math.h>

#define B_    4
#define N_    8192
#define D_    64
#define S_    1024
#define K_    32
#define CIN_  134
#define HID_  128
#define COUT_ 256
#define C8_   32
#define P_    131072   // B_*S_*K_
#define CTOT_ 518
#define NEG_INF_ (-3.402823466e38f)
#define CS_   (COUT_*S_)
#define NBLK_ 1024     // conv GEMM grid.x (P_/128)

// ---------------- scratch (device globals; no allocations allowed) --------
__device__ float g_Y [(size_t)CTOT_ * P_];
__device__ float g_Xs[(size_t)COUT_ * P_];
__device__ float g_Wt[300000];
__device__ float4 g_prm[CTOT_];
__device__ float g_feat[B_*COUT_*S_];
__device__ float g_q[B_*C8_*S_];
__device__ float g_k[B_*C8_*S_];
__device__ float g_v[B_*COUT_*S_];
__device__ float g_E [(size_t)B_*S_*S_];
__device__ float g_Ec[B_*COUT_*COUT_];
__device__ float g_Ecp[4*B_*COUT_*COUT_];
__device__ float g_opp[(size_t)4*B_*CS_];
__device__ float g_ocp[(size_t)4*B_*CS_];
__device__ float g_sp1[COUT_*NBLK_];
__device__ float g_sp2[COUT_*NBLK_];
__device__ float g_mean[COUT_];
__device__ float g_istd[COUT_];
__device__ int   g_fps [B_*S_];
__device__ float g_nxyz[B_*S_*3];
__device__ int   g_ball[B_*S_*K_];

// ---------------- FPS (redux.sync argmax, one barrier per iteration) --------
__global__ void fps_kernel(const float* __restrict__ xyz, float* __restrict__ outxyz)
{
    int b = blockIdx.x;
    const float* X = xyz + (size_t)b * N_ * 3;
    int tid = threadIdx.x;                 // 1024 threads
    int lane = tid & 31, wid = tid >> 5;
    float px[8], py[8], pz[8], dist[8];
#pragma unroll
    for (int i = 0; i < 8; i++){
        int j = tid + i * 1024;
        px[i] = X[j*3+0]; py[i] = X[j*3+1]; pz[i] = X[j*3+2];
        dist[i] = 1e10f;
    }
    __shared__ unsigned s_v[2][32];
    __shared__ unsigned s_i[2][32];
    float cx = X[0], cy = X[1], cz = X[2];
    int   far = 0;
    int   p = 0;

    for (int t = 0; t < S_; t++){
        if (tid == 0){
            g_fps[b*S_ + t] = far;
            g_nxyz[(b*S_+t)*3+0] = cx;
            g_nxyz[(b*S_+t)*3+1] = cy;
            g_nxyz[(b*S_+t)*3+2] = cz;
            outxyz[(b*S_+t)*3+0] = cx;
            outxyz[(b*S_+t)*3+1] = cy;
            outxyz[(b*S_+t)*3+2] = cz;
        }
        float bv = -1.0f; int bi = 0;
#pragma unroll
        for (int i = 0; i < 8; i++){
            float dx = px[i]-cx, dy = py[i]-cy, dz = pz[i]-cz;
            float d = fmaf(dz, dz, fmaf(dy, dy, dx*dx));
            float nd = fminf(dist[i], d);
            dist[i] = nd;
            if (nd > bv){ bv = nd; bi = tid + i*1024; }
        }
        unsigned vb = __float_as_uint(bv);
        unsigned mx = __reduce_max_sync(0xffffffffu, vb);
        unsigned im = (vb == mx) ? (unsigned)bi : 0xFFFFFFFFu;
        unsigned mn = __reduce_min_sync(0xffffffffu, im);
        if (lane == 0){ s_v[p][wid] = mx; s_i[p][wid] = mn; }
        __syncthreads();
        vb = s_v[p][lane];
        unsigned ib = s_i[p][lane];
        mx = __reduce_max_sync(0xffffffffu, vb);
        im = (vb == mx) ? ib : 0xFFFFFFFFu;
        mn = __reduce_min_sync(0xffffffffu, im);
        far = (int)mn;
        cx = X[far*3+0]; cy = X[far*3+1]; cz = X[far*3+2];
        p ^= 1;
    }
}

// ------ ball query (blocks <512) + weight transpose / prm init (rest) -------
__global__ void ball_prep(const float* __restrict__ xyz,
                          const float* __restrict__ W0, const float* __restrict__ W1,
                          const float* __restrict__ W2, const float* __restrict__ W3)
{
    if (blockIdx.x >= 512){
        int i = (blockIdx.x - 512) * 256 + threadIdx.x;
        if (i < CTOT_) g_prm[i] = make_float4(0.f, 1.f, 0.f, NEG_INF_);
        const int   Ms[4] = {HID_, HID_, HID_, COUT_};
        const int   Ks[4] = {CIN_, CIN_+HID_, CIN_+2*HID_, CIN_+3*HID_};
        const float* Ws[4] = {W0, W1, W2, W3};
        long off = 0;
#pragma unroll
        for (int l = 0; l < 4; l++){
            int n = Ms[l]*Ks[l];
            if (i >= 0 && i < n){
                int m = i / Ks[l], k = i - m*Ks[l];
                g_Wt[off + (long)k*Ms[l] + m] = Ws[l][i];
            }
            i -= n;
            off += n;
        }
        return;
    }
    int gw   = (blockIdx.x * blockDim.x + threadIdx.x) >> 5;
    int lane = threadIdx.x & 31;
    int b = gw >> 10;
    const float* X = xyz + (size_t)b * N_ * 3;
    float cx = g_nxyz[gw*3+0], cy = g_nxyz[gw*3+1], cz = g_nxyz[gw*3+2];
    float cn2 = __fadd_rn(__fadd_rn(__fmul_rn(cx,cx), __fmul_rn(cy,cy)), __fmul_rn(cz,cz));
    int* out = g_ball + gw * K_;
    int cnt = 0;
    for (int base = 0; base < N_ && cnt < K_; base += 256){
        float xx[8], yy[8], zz[8];
#pragma unroll
        for (int i = 0; i < 8; i++){
            int j = base + i*32 + lane;
            xx[i] = X[j*3+0]; yy[i] = X[j*3+1]; zz[i] = X[j*3+2];
        }
        float d[8];
#pragma unroll
        for (int i = 0; i < 8; i++){
            float pn2 = __fadd_rn(__fadd_rn(__fmul_rn(xx[i],xx[i]), __fmul_rn(yy[i],yy[i])),
                                  __fmul_rn(zz[i],zz[i]));
            float dt  = fmaf(cz, zz[i], fmaf(cy, yy[i], __fmul_rn(cx, xx[i])));
            d[i] = __fsub_rn(__fadd_rn(cn2, pn2), __fmul_rn(2.0f, dt));
        }
#pragma unroll
        for (int i = 0; i < 8; i++){
            bool inb = !(d[i] > 0.04f);
            unsigned msk = __ballot_sync(0xffffffffu, inb);
            int pos = cnt + __popc(msk & ((1u << lane) - 1u));
            if (inb && pos < K_) out[pos] = base + i*32 + lane;
            cnt += __popc(msk);
        }
    }
    __syncwarp();
    if (cnt < K_){
        int first = out[0];
        for (int pq = cnt + lane; pq < K_; pq += 32) out[pq] = first;
    }
}

// ---------------- build x0 into g_Y channels [0,134) ------------------------
__global__ void build_x0(const float* __restrict__ xyz, const float* __restrict__ pts)
{
    int bs  = blockIdx.x;
    int b   = bs >> 10;
    int tid = threadIdx.x;                  // 256
    __shared__ int   sj[32];
    __shared__ float sgx[32], sgy[32], sgz[32];
    __shared__ float scp[64];
    __shared__ float scen[3];
    if (tid < 32){
        int j = g_ball[bs*K_ + tid]; sj[tid] = j;
        const float* Xp = xyz + ((size_t)b*N_ + j)*3;
        sgx[tid] = Xp[0]; sgy[tid] = Xp[1]; sgz[tid] = Xp[2];
    } else if (tid < 96){
        scp[tid-32] = pts[((size_t)b*N_ + g_fps[bs])*D_ + (tid-32)];
    } else if (tid < 99){
        scen[tid-96] = g_nxyz[bs*3 + (tid-96)];
    }
    __syncthreads();
    const float* Pb = pts + (size_t)b * N_ * D_;
    size_t pbase = (size_t)bs * K_;
    for (int idx = tid; idx < CIN_ * K_; idx += 256){
        int c = idx >> 5, k = idx & 31;
        int j = sj[k];
        float val;
        if (c < 3){
            float g = (c==0) ? sgx[k] : (c==1) ? sgy[k] : sgz[k];
            float cc = scen[c];
            val = (g - cc) - cc;
        } else if (c < 67){
            val = Pb[(size_t)j*D_ + (c-3)] - scp[c-3];
        } else if (c < 70){
            int c3 = c - 67;
            float g = (c3==0) ? sgx[k] : (c3==1) ? sgy[k] : sgz[k];
            val = g - scen[c3];
        } else {
            val = Pb[(size_t)j*D_ + (c-70)];
        }
        g_Y[(size_t)c*P_ + pbase + k] = val;
    }
}

// ---------------- tf32 helpers ------------------------------------------------
__device__ __forceinline__ unsigned hi_tf(float x){
    return __float_as_uint(x) & 0xFFFFE000u;
}
__device__ __forceinline__ void mma_tf32(float* d, const unsigned* a, const unsigned* b){
    asm volatile(
        "mma.sync.aligned.m16n8k8.row.col.f32.tf32.tf32.f32 "
        "{%0,%1,%2,%3}, {%4,%5,%6,%7}, {%8,%9}, {%0,%1,%2,%3};"
        : "+f"(d[0]), "+f"(d[1]), "+f"(d[2]), "+f"(d[3])
        : "r"(a[0]), "r"(a[1]), "r"(a[2]), "r"(a[3]), "r"(b[0]), "r"(b[1]));
}

#define SMP_ 136

#define TC_COMPUTE(AS, BS)                                                    \
    {                                                                         \
        unsigned ah[16], al[16], bh[8], bl[8];                                \
        _Pragma("unroll")                                                     \
        for (int mt = 0; mt < 4; mt++){                                       \
            int mb = wm + mt*16 + g;                                          \
            float x0 = AS[tig  ][mb];                                         \
            float x1 = AS[tig  ][mb+8];                                       \
            float x2 = AS[tig+4][mb];                                         \
            float x3 = AS[tig+4][mb+8];                                       \
            unsigned h;                                                       \
            h = hi_tf(x0); ah[mt*4+0] = h; al[mt*4+0] = __float_as_uint(x0 - __uint_as_float(h)); \
            h = hi_tf(x1); ah[mt*4+1] = h; al[mt*4+1] = __float_as_uint(x1 - __uint_as_float(h)); \
            h = hi_tf(x2); ah[mt*4+2] = h; al[mt*4+2] = __float_as_uint(x2 - __uint_as_float(h)); \
            h = hi_tf(x3); ah[mt*4+3] = h; al[mt*4+3] = __float_as_uint(x3 - __uint_as_float(h)); \
        }                                                                     \
        _Pragma("unroll")                                                     \
        for (int nt = 0; nt < 4; nt++){                                       \
            int nb = wn + nt*8 + g;                                           \
            float y0 = BS[tig  ][nb];                                         \
            float y1 = BS[tig+4][nb];                                         \
            unsigned h;                                                       \
            h = hi_tf(y0); bh[nt*2+0] = h; bl[nt*2+0] = __float_as_uint(y0 - __uint_as_float(h)); \
            h = hi_tf(y1); bh[nt*2+1] = h; bl[nt*2+1] = __float_as_uint(y1 - __uint_as_float(h)); \
        }                                                                     \
        _Pragma("unroll")                                                     \
        for (int mt = 0; mt < 4; mt++)                                        \
            _Pragma("unroll")                                                 \
            for (int nt = 0; nt < 4; nt++)                                    \
                mma_tf32(acc[mt][nt], ah + mt*4, bh + nt*2);                  \
        _Pragma("unroll")                                                     \
        for (int mt = 0; mt < 4; mt++)                                        \
            _Pragma("unroll")                                                 \
            for (int nt = 0; nt < 4; nt++)                                    \
                mma_tf32(acc[mt][nt], ah + mt*4, bl + nt*2);                  \
        _Pragma("unroll")                                                     \
        for (int mt = 0; mt < 4; mt++)                                        \
            _Pragma("unroll")                                                 \
            for (int nt = 0; nt < 4; nt++)                                    \
                mma_tf32(acc[mt][nt], al + mt*4, bh + nt*2);                  \
    }

// ------- 3xTF32 conv GEMM (k-tile 8, R14 schedule) + fused BN-stat partials --
__global__ void __launch_bounds__(256)
gemm_tc(const float* __restrict__ At, const float* __restrict__ Bm,
        float* __restrict__ C, const float4* __restrict__ prm,
        int M, int Nn, int Kk)
{
    __shared__ float As[2][8][SMP_];
    __shared__ float Bs[2][8][SMP_];
    __shared__ float ssum[2][4][64], sssq[2][4][64];
    int tid = threadIdx.x, lane = tid & 31, wid = tid >> 5;
    int n0 = blockIdx.x * 128, m0 = blockIdx.y * 128;
    int kr = wid;
    int c4 = lane << 2;
    int wm = (wid >> 2) * 64;
    int wn = (wid & 3) * 32;
    int g = lane >> 2, tig = lane & 3;
    int ntiles = (Kk + 7) >> 3;

    const float4 z4 = make_float4(0.f,0.f,0.f,0.f);

    {
        float4 av = z4, bv = z4;
        if (kr < Kk){
            av = *(const float4*)(At + (long)kr*M  + m0 + c4);
            bv = *(const float4*)(Bm + (long)kr*Nn + n0 + c4);
            float4 pp = prm[kr];
            bv.x = fmaxf((bv.x - pp.x)*pp.y + pp.z, pp.w);
            bv.y = fmaxf((bv.y - pp.x)*pp.y + pp.z, pp.w);
            bv.z = fmaxf((bv.z - pp.x)*pp.y + pp.z, pp.w);
            bv.w = fmaxf((bv.w - pp.x)*pp.y + pp.z, pp.w);
        }
        *(float4*)&As[0][kr][c4] = av;
        *(float4*)&Bs[0][kr][c4] = bv;
    }
    __syncthreads();

    float acc[4][4][4];
#pragma unroll
    for (int mt = 0; mt < 4; mt++)
#pragma unroll
        for (int nt = 0; nt < 4; nt++)
#pragma unroll
            for (int r = 0; r < 4; r++) acc[mt][nt][r] = 0.f;

    int buf = 0;
    for (int t = 1; t <= ntiles; t++){
        float4 av = z4, bv = z4;
        bool have = (t < ntiles);
        if (have){
            int kg = t*8 + kr;
            if (kg < Kk){
                av = *(const float4*)(At + (long)kg*M  + m0 + c4);
                bv = *(const float4*)(Bm + (long)kg*Nn + n0 + c4);
                float4 pp = prm[kg];
                bv.x = fmaxf((bv.x - pp.x)*pp.y + pp.z, pp.w);
                bv.y = fmaxf((bv.y - pp.x)*pp.y + pp.z, pp.w);
                bv.z = fmaxf((bv.z - pp.x)*pp.y + pp.z, pp.w);
                bv.w = fmaxf((bv.w - pp.x)*pp.y + pp.z, pp.w);
            }
        }
        TC_COMPUTE(As[buf], Bs[buf]);
        if (have){
            int nb = buf ^ 1;
            *(float4*)&As[nb][kr][c4] = av;
            *(float4*)&Bs[nb][kr][c4] = bv;
            __syncthreads();
            buf ^= 1;
        }
    }

    // ---- epilogue: C writes + per-channel stat partials ----
#pragma unroll
    for (int mt = 0; mt < 4; mt++){
        int r0 = m0 + wm + mt*16 + g;
        int r1 = r0 + 8;
#pragma unroll
        for (int nt = 0; nt < 4; nt++){
            int cc = n0 + wn + nt*8 + tig*2;
            *(float2*)&C[(long)r0*Nn + cc] = make_float2(acc[mt][nt][0], acc[mt][nt][1]);
            *(float2*)&C[(long)r1*Nn + cc] = make_float2(acc[mt][nt][2], acc[mt][nt][3]);
        }
        float s0 = 0.f, s1 = 0.f, q0 = 0.f, q1 = 0.f;
#pragma unroll
        for (int nt = 0; nt < 4; nt++){
            s0 += acc[mt][nt][0] + acc[mt][nt][1];
            s1 += acc[mt][nt][2] + acc[mt][nt][3];
            q0 = fmaf(acc[mt][nt][0], acc[mt][nt][0], q0);
            q0 = fmaf(acc[mt][nt][1], acc[mt][nt][1], q0);
            q1 = fmaf(acc[mt][nt][2], acc[mt][nt][2], q1);
            q1 = fmaf(acc[mt][nt][3], acc[mt][nt][3], q1);
        }
        s0 += __shfl_xor_sync(0xffffffffu, s0, 1);
        s0 += __shfl_xor_sync(0xffffffffu, s0, 2);
        s1 += __shfl_xor_sync(0xffffffffu, s1, 1);
        s1 += __shfl_xor_sync(0xffffffffu, s1, 2);
        q0 += __shfl_xor_sync(0xffffffffu, q0, 1);
        q0 += __shfl_xor_sync(0xffffffffu, q0, 2);
        q1 += __shfl_xor_sync(0xffffffffu, q1, 1);
        q1 += __shfl_xor_sync(0xffffffffu, q1, 2);
        if (tig == 0){
            int half = wm >> 6, ws = wn >> 5;
            ssum[half][ws][mt*16 + g]     = s0;
            ssum[half][ws][mt*16 + g + 8] = s1;
            sssq[half][ws][mt*16 + g]     = q0;
            sssq[half][ws][mt*16 + g + 8] = q1;
        }
    }
    __syncthreads();
    if (tid < 128){
        int half = tid >> 6, lr = tid & 63;
        float s = (ssum[half][0][lr] + ssum[half][1][lr])
                + (ssum[half][2][lr] + ssum[half][3][lr]);
        float qq = (sssq[half][0][lr] + sssq[half][1][lr])
                 + (sssq[half][2][lr] + sssq[half][3][lr]);
        int ch = m0 + tid;
        g_sp1[(long)ch*NBLK_ + blockIdx.x] = s;
        g_sp2[(long)ch*NBLK_ + blockIdx.x] = qq;
    }
}

// ---- reduce stat partials (fixed order, f64) + publish BN params ------------
__global__ void bn_reduce(int coff, const float* __restrict__ gg,
                          const float* __restrict__ be)
{
    int c = blockIdx.x;
    int tid = threadIdx.x;
    double s = 0.0, ss = 0.0;
    for (int j = tid; j < NBLK_; j += 256){
        s  += (double)g_sp1[(long)c*NBLK_ + j];
        ss += (double)g_sp2[(long)c*NBLK_ + j];
    }
    __shared__ double sh0[256], sh1[256];
    sh0[tid] = s; sh1[tid] = ss; __syncthreads();
    for (int off = 128; off; off >>= 1){
        if (tid < off){ sh0[tid] += sh0[tid+off]; sh1[tid] += sh1[tid+off]; }
        __syncthreads();
    }
    if (tid == 0){
        double m   = sh0[0] / (double)P_;
        double var = sh1[0] / (double)P_ - m*m;
        float mf = (float)m;
        float isf = (float)(1.0 / sqrt(var + 1e-5));
        g_mean[c] = mf;
        g_istd[c] = isf;
        if (coff >= 0)
            g_prm[coff + c] = make_float4(mf, isf * gg[c], be[c], 0.f);
    }
}

// ------- 3xTF32 GEMM with K-split: A row-major; B row-major or K-major -------
__global__ void __launch_bounds__(256)
gemm_tc2s(const float* __restrict__ A, const float* __restrict__ Bm,
          float* __restrict__ Cp,
          int M, int Nn, int Kk, int lda, int ldb, int bRow, int NC,
          long sA, long sB)
{
    int z = blockIdx.z;
    int b = z / NC, kc = z - b*NC;
    A  += (long)b * sA + (long)kc * Kk;
    Bm += (long)b * sB + (bRow ? (long)kc * Kk : (long)kc * Kk * Nn);
    float* C = Cp + (long)z * M * Nn;
    __shared__ float As[2][8][SMP_];
    __shared__ float Bs[2][8][SMP_];
    int tid = threadIdx.x, lane = tid & 31, wid = tid >> 5;
    int n0 = blockIdx.x * 128, m0 = blockIdx.y * 128;
    int mf = tid & 127, kq = (tid >> 7) << 2;
    int kr = wid, c4 = lane << 2;
    int wm = (wid >> 2) * 64;
    int wn = (wid & 3) * 32;
    int g = lane >> 2, tig = lane & 3;
    int ntiles = Kk >> 3;

    {
        float4 av = *(const float4*)(A + (long)(m0+mf)*lda + kq);
#pragma unroll
        for (int i = 0; i < 4; i++) As[0][kq+i][mf] = ((float*)&av)[i];
        if (bRow){
            float4 bv = *(const float4*)(Bm + (long)(n0+mf)*ldb + kq);
#pragma unroll
            for (int i = 0; i < 4; i++) Bs[0][kq+i][mf] = ((float*)&bv)[i];
        } else {
            float4 bv = *(const float4*)(Bm + (long)kr*Nn + n0 + c4);
            *(float4*)&Bs[0][kr][c4] = bv;
        }
    }
    __syncthreads();

    float acc[4][4][4];
#pragma unroll
    for (int mt = 0; mt < 4; mt++)
#pragma unroll
        for (int nt = 0; nt < 4; nt++)
#pragma unroll
            for (int r = 0; r < 4; r++) acc[mt][nt][r] = 0.f;

    int buf = 0;
    for (int t = 1; t <= ntiles; t++){
        float4 av, bv;
        bool have = (t < ntiles);
        if (have){
            int k0 = t*8;
            av = *(const float4*)(A + (long)(m0+mf)*lda + k0 + kq);
            if (bRow) bv = *(const float4*)(Bm + (long)(n0+mf)*ldb + k0 + kq);
            else      bv = *(const float4*)(Bm + (long)(k0+kr)*Nn + n0 + c4);
        }
        TC_COMPUTE(As[buf], Bs[buf]);
        if (have){
            int nb = buf ^ 1;
#pragma unroll
            for (int i = 0; i < 4; i++) As[nb][kq+i][mf] = ((float*)&av)[i];
            if (bRow){
#pragma unroll
                for (int i = 0; i < 4; i++) Bs[nb][kq+i][mf] = ((float*)&bv)[i];
            } else {
                *(float4*)&Bs[nb][kr][c4] = bv;
            }
            __syncthreads();
            buf ^= 1;
        }
    }

#pragma unroll
    for (int mt = 0; mt < 4; mt++){
        int r0 = m0 + wm + mt*16 + g;
        int r1 = r0 + 8;
#pragma unroll
        for (int nt = 0; nt < 4; nt++){
            int cc = n0 + wn + nt*8 + tig*2;
            *(float2*)&C[(long)r0*Nn + cc] = make_float2(acc[mt][nt][0], acc[mt][nt][1]);
            *(float2*)&C[(long)r1*Nn + cc] = make_float2(acc[mt][nt][2], acc[mt][nt][3]);
        }
    }
}

// ---------------- fused q/k projection (64x64 tile) --------------------------
__global__ void gemm_qk(const float* __restrict__ Wq, const float* __restrict__ Wk,
                        const float* __restrict__ bq, const float* __restrict__ bk,
                        const float* __restrict__ feat,
                        float* __restrict__ qout, float* __restrict__ kout)
{
    int z = blockIdx.z, b = z >> 1, sel = z & 1;
    const float* A    = sel ? Wk : Wq;
    const float* bias = sel ? bk : bq;
    const float* Bm = feat + (long)b*CS_;
    float* C = (sel ? kout : qout) + (long)b*C8_*S_;
    const int M = C8_, Nn = S_, Kk = COUT_;
    __shared__ float As[16][68];
    __shared__ float Bs[16][64];
    int tid = threadIdx.x;
    int m0 = 0, n0 = blockIdx.x * 64;
    int ty = tid >> 4, tx = tid & 15;
    float acc[4][4] = {};
    for (int k0 = 0; k0 < Kk; k0 += 16){
#pragma unroll
        for (int i = tid; i < 1024; i += 256){
            int rr = i >> 4, cc = i & 15;
            int mm = m0 + rr, kk = k0 + cc;
            As[cc][rr] = (mm < M) ? A[(long)mm*Kk + kk] : 0.f;
        }
#pragma unroll
        for (int i = tid; i < 1024; i += 256){
            int rr = i >> 6, cc = i & 63;
            int kk = k0 + rr;
            Bs[rr][cc] = Bm[(long)kk*Nn + n0 + cc];
        }
        __syncthreads();
#pragma unroll
        for (int kk = 0; kk < 16; kk++){
            float4 a  = *(const float4*)&As[kk][ty*4];
            float4 bv = *(const float4*)&Bs[kk][tx*4];
            float av[4] = {a.x, a.y, a.z, a.w};
            float bb[4] = {bv.x, bv.y, bv.z, bv.w};
#pragma unroll
            for (int i = 0; i < 4; i++)
#pragma unroll
                for (int j = 0; j < 4; j++)
                    acc[i][j] = fmaf(av[i], bb[j], acc[i][j]);
        }
        __syncthreads();
    }
#pragma unroll
    for (int i = 0; i < 4; i++){
        int mm = m0 + ty*4 + i;
        if (mm < M){
            float bsv = bias[mm];
            float4 o = make_float4(acc[i][0]+bsv, acc[i][1]+bsv, acc[i][2]+bsv, acc[i][3]+bsv);
            *(float4*)&C[(long)mm*Nn + n0 + tx*4] = o;
        }
    }
}

// ---------------- small GEMMs (64x64 tile) -----------------------------------
__global__ void gemm_nn(const float* __restrict__ A, const float* __restrict__ Bm,
                        float* __restrict__ C, const float* __restrict__ bias,
                        int M, int Nn, int Kk, long sA, long sB, long sC)
{
    A  += (long)blockIdx.z * sA;
    Bm += (long)blockIdx.z * sB;
    C  += (long)blockIdx.z * sC;
    __shared__ float As[16][68];
    __shared__ float Bs[16][64];
    int tid = threadIdx.x;
    int m0 = blockIdx.y * 64, n0 = blockIdx.x * 64;
    int ty = tid >> 4, tx = tid & 15;
    float acc[4][4] = {};
    for (int k0 = 0; k0 < Kk; k0 += 16){
#pragma unroll
        for (int i = tid; i < 1024; i += 256){
            int rr = i >> 4, cc = i & 15;
            int mm = m0 + rr, kk = k0 + cc;
            As[cc][rr] = (mm < M && kk < Kk) ? A[(long)mm*Kk + kk] : 0.f;
        }
#pragma unroll
        for (int i = tid; i < 1024; i += 256){
            int rr = i >> 6, cc = i & 63;
            int kk = k0 + rr;
            Bs[rr][cc] = (kk < Kk) ? Bm[(long)kk*Nn + n0 + cc] : 0.f;
        }
        __syncthreads();
#pragma unroll
        for (int kk = 0; kk < 16; kk++){
            float4 a  = *(const float4*)&As[kk][ty*4];
            float4 bv = *(const float4*)&Bs[kk][tx*4];
            float av[4] = {a.x, a.y, a.z, a.w};
            float bb[4] = {bv.x, bv.y, bv.z, bv.w};
#pragma unroll
            for (int i = 0; i < 4; i++)
#pragma unroll
                for (int j = 0; j < 4; j++)
                    acc[i][j] = fmaf(av[i], bb[j], acc[i][j]);
        }
        __syncthreads();
    }
#pragma unroll
    for (int i = 0; i < 4; i++){
        int mm = m0 + ty*4 + i;
        if (mm < M){
            float bsv = bias ? bias[mm] : 0.f;
            float4 o = make_float4(acc[i][0]+bsv, acc[i][1]+bsv, acc[i][2]+bsv, acc[i][3]+bsv);
            *(float4*)&C[(long)mm*Nn + n0 + tx*4] = o;
        }
    }
}

__global__ void gemm_tn(const float* __restrict__ A, const float* __restrict__ Bm,
                        float* __restrict__ C,
                        int M, int Nn, int Kk, int lda, int ldb,
                        long sA, long sB, long sC)
{
    A += (long)blockIdx.z*sA; Bm += (long)blockIdx.z*sB; C += (long)blockIdx.z*sC;
    __shared__ float As[16][64], Bs[16][64];
    int tid = threadIdx.x;
    int m0 = blockIdx.y * 64, n0 = blockIdx.x * 64;
    int ty = tid >> 4, tx = tid & 15;
    float acc[4][4] = {};
    for (int k0 = 0; k0 < Kk; k0 += 16){
#pragma unroll
        for (int i = tid; i < 1024; i += 256){
            int rr = i >> 6, cc = i & 63;
            int kk = k0 + rr;
            As[rr][cc] = (kk < Kk) ? A[(long)kk*lda + m0 + cc] : 0.f;
            Bs[rr][cc] = (kk < Kk) ? Bm[(long)kk*ldb + n0 + cc] : 0.f;
        }
        __syncthreads();
#pragma unroll
        for (int kk = 0; kk < 16; kk++){
            float4 a  = *(const float4*)&As[kk][ty*4];
            float4 bv = *(const float4*)&Bs[kk][tx*4];
            float av[4] = {a.x, a.y, a.z, a.w};
            float bb[4] = {bv.x, bv.y, bv.z, bv.w};
#pragma unroll
            for (int i = 0; i < 4; i++)
#pragma unroll
                for (int j = 0; j < 4; j++)
                    acc[i][j] = fmaf(av[i], bb[j], acc[i][j]);
        }
        __syncthreads();
    }
#pragma unroll
    for (int i = 0; i < 4; i++){
        int mm = m0 + ty*4 + i;
        float4 o = make_float4(acc[i][0], acc[i][1], acc[i][2], acc[i][3]);
        *(float4*)&C[(long)mm*Nn + n0 + tx*4] = o;
    }
}

// ---- K-split Kahan NT GEMM for energy_c -------------------------------------
__global__ void ec_kah_split(const float* __restrict__ feat, float* __restrict__ Ecp)
{
    int z = blockIdx.z;
    int b = z >> 2, kc = z & 3;
    const float* A = feat + (long)b*CS_ + kc*256;
    float* C = Ecp + ((long)kc*B_ + b) * COUT_*COUT_;
    __shared__ float As[16][68], Bs[16][68];
    int tid = threadIdx.x;
    int m0 = blockIdx.y * 64, n0 = blockIdx.x * 64;
    int ty = tid >> 4, tx = tid & 15;
    float acc[4][4] = {};
    float cmp[4][4] = {};
    for (int k0 = 0; k0 < 256; k0 += 16){
#pragma unroll
        for (int i = tid; i < 1024; i += 256){
            int mm = i >> 4, kd = i & 15;
            int kk = k0 + kd;
            As[kd][mm] = A[(long)(m0+mm)*S_ + kk];
            Bs[kd][mm] = A[(long)(n0+mm)*S_ + kk];
        }
        __syncthreads();
#pragma unroll
        for (int kk = 0; kk < 16; kk++){
            float4 a  = *(const float4*)&As[kk][ty*4];
            float4 bv = *(const float4*)&Bs[kk][tx*4];
            float av[4] = {a.x, a.y, a.z, a.w};
            float bb[4] = {bv.x, bv.y, bv.z, bv.w};
#pragma unroll
            for (int i = 0; i < 4; i++)
#pragma unroll
                for (int j = 0; j < 4; j++){
                    float y = fmaf(av[i], bb[j], -cmp[i][j]);
                    float t = acc[i][j] + y;
                    cmp[i][j] = (t - acc[i][j]) - y;
                    acc[i][j] = t;
                }
        }
        __syncthreads();
    }
#pragma unroll
    for (int i = 0; i < 4; i++){
        int mm = m0 + ty*4 + i;
        float4 o = make_float4(acc[i][0], acc[i][1], acc[i][2], acc[i][3]);
        *(float4*)&C[(long)mm*COUT_ + n0 + tx*4] = o;
    }
}

// ------- fused layer-4 BN + ReLU + max over K --------------------------------
__global__ void bn_relu_maxk(const float* __restrict__ Xs,
                             const float* __restrict__ gg, const float* __restrict__ be)
{
    int i = blockIdx.x * 256 + threadIdx.x;
    int s = i & 1023, c = (i >> 10) & 255, b = i >> 18;
    float m = g_mean[c], is = g_istd[c], gv = gg[c], bb = be[c];
    float sc = is * gv;
    const float4* src = (const float4*)(Xs + (size_t)c * P_ + ((size_t)(b*S_ + s)) * K_);
    float best = 0.f;
#pragma unroll
    for (int k = 0; k < 8; k++){
        float4 v = src[k];
        best = fmaxf(best, (v.x - m)*sc + bb);
        best = fmaxf(best, (v.y - m)*sc + bb);
        best = fmaxf(best, (v.z - m)*sc + bb);
        best = fmaxf(best, (v.w - m)*sc + bb);
    }
    g_feat[i] = best;
}

// ---------------- softmaxes ---------------------------------------------------
__global__ void softmax_rows_1024(float* __restrict__ E)
{
    int row = blockIdx.x;
    float* e = E + (size_t)row * 1024;
    int tid = threadIdx.x;
    __shared__ float sh[256];
    float mx = -3.402823466e38f;
    for (int c = tid; c < 1024; c += 256) mx = fmaxf(mx, e[c]);
    sh[tid] = mx; __syncthreads();
    for (int off = 128; off; off >>= 1){ if (tid < off) sh[tid] = fmaxf(sh[tid], sh[tid+off]); __syncthreads(); }
    mx = sh[0]; __syncthreads();
    float sum = 0.f;
    float vals[4];
#pragma unroll
    for (int q = 0; q < 4; q++){
        int c = tid + q*256;
        float v = expf(e[c] - mx);
        vals[q] = v; sum += v;
    }
    sh[tid] = sum; __syncthreads();
    for (int off = 128; off; off >>= 1){ if (tid < off) sh[tid] += sh[tid+off]; __syncthreads(); }
    float inv = 1.0f / sh[0];
#pragma unroll
    for (int q = 0; q < 4; q++) e[tid + q*256] = vals[q] * inv;
}

// channel softmax fused with partial combine (fixed f64 order)
__global__ void softmax_c_kernel(const float* __restrict__ Ecp, float* __restrict__ Ecout)
{
    int row = blockIdx.x;
    int i = row * 256 + threadIdx.x;
    const long NB = (long)B_*COUT_*COUT_;
    int tid = threadIdx.x;
    __shared__ double sh[256];
    double v = ((double)Ecp[i] + (double)Ecp[i + NB])
             + ((double)Ecp[i + 2*NB] + (double)Ecp[i + 3*NB]);
    v = (double)(float)v;
    sh[tid] = v; __syncthreads();
    for (int off = 128; off; off >>= 1){ if (tid < off) sh[tid] = fmax(sh[tid], sh[tid+off]); __syncthreads(); }
    double m1 = sh[0]; __syncthreads();
    double t = m1 - v;
    sh[tid] = t; __syncthreads();
    for (int off = 128; off; off >>= 1){ if (tid < off) sh[tid] = fmax(sh[tid], sh[tid+off]); __syncthreads(); }
    double mt = sh[0]; __syncthreads();
    double ex = exp(t - mt);
    sh[tid] = ex; __syncthreads();
    for (int off = 128; off; off >>= 1){ if (tid < off) sh[tid] += sh[tid+off]; __syncthreads(); }
    Ecout[i] = (float)(ex / sh[0]);
}

// ---------------- finalize: combine K-chunk partials + compose output --------
__global__ void finalize_kernel(float* __restrict__ out, const float* __restrict__ gamma)
{
    int i = blockIdx.x * 256 + threadIdx.x;
    int c = i & 255, s = (i >> 8) & 1023, b = i >> 18;
    long f = ((long)(b*COUT_ + c)) * S_ + s;
    long r = (long)c * S_ + s;
    long zb = (long)b * 4;
    double sp = ((double)g_opp[(zb+0)*CS_ + r] + (double)g_opp[(zb+1)*CS_ + r])
              + ((double)g_opp[(zb+2)*CS_ + r] + (double)g_opp[(zb+3)*CS_ + r]);
    double sc = ((double)g_ocp[(zb+0)*CS_ + r] + (double)g_ocp[(zb+1)*CS_ + r])
              + ((double)g_ocp[(zb+2)*CS_ + r] + (double)g_ocp[(zb+3)*CS_ + r]);
    float outp = (float)sp, outc = (float)sc;
    float g = gamma[0];
    float val = g * (outp + outc) + 2.0f * g_feat[f];
    out[(size_t)B_*S_*3 + i] = val;
}

// ---------------- launch -------------------------------------------------------
extern "C" void kernel_launch(void* const* d_in, const int* in_sizes, int n_in,
                              void* d_out, int out_size)
{
    const float* xyz    = (const float*)d_in[0];
    const float* points = (const float*)d_in[1];
    const float* W[4]  = {(const float*)d_in[2],  (const float*)d_in[6],
                          (const float*)d_in[10], (const float*)d_in[14]};
    const float* gl[4] = {(const float*)d_in[4],  (const float*)d_in[8],
                          (const float*)d_in[12], (const float*)d_in[16]};
    const float* bel[4]= {(const float*)d_in[5],  (const float*)d_in[9],
                          (const float*)d_in[13], (const float*)d_in[17]};
    const float* Wq = (const float*)d_in[18]; const float* bq = (const float*)d_in[19];
    const float* Wk = (const float*)d_in[20]; const float* bk = (const float*)d_in[21];
    const float* Wv = (const float*)d_in[22]; const float* bv = (const float*)d_in[23];
    const float* gamma = (const float*)d_in[24];
    float* out = (float*)d_out;

    float *Y, *Xs, *Wt, *feat, *q, *k, *v, *E, *Ec, *Ecp, *opp, *ocp;
    float4* prm;
    cudaGetSymbolAddress((void**)&Y,    g_Y);
    cudaGetSymbolAddress((void**)&Xs,   g_Xs);
    cudaGetSymbolAddress((void**)&Wt,   g_Wt);
    cudaGetSymbolAddress((void**)&prm,  g_prm);
    cudaGetSymbolAddress((void**)&feat, g_feat);
    cudaGetSymbolAddress((void**)&q,    g_q);
    cudaGetSymbolAddress((void**)&k,    g_k);
    cudaGetSymbolAddress((void**)&v,    g_v);
    cudaGetSymbolAddress((void**)&E,    g_E);
    cudaGetSymbolAddress((void**)&Ec,   g_Ec);
    cudaGetSymbolAddress((void**)&Ecp,  g_Ecp);
    cudaGetSymbolAddress((void**)&opp,  g_opp);
    cudaGetSymbolAddress((void**)&ocp,  g_ocp);

    int   Kl[4]  = {CIN_, CIN_+HID_, CIN_+2*HID_, CIN_+3*HID_};
    int   COl[4] = {HID_, HID_, HID_, COUT_};
    long Woff[4];
    {
        long o = 0;
        for (int l = 0; l < 4; l++){ Woff[l] = o; o += (long)Kl[l]*COl[l]; }
    }

    // launch order: fps(1), ball_prep(2), build_x0(3), gemm_tc L1(4) <- profiled
    fps_kernel<<<B_, 1024>>>(xyz, out);
    ball_prep<<<512 + (233216 + 255)/256, 256>>>(xyz, W[0], W[1], W[2], W[3]);
    build_x0<<<B_*S_, 256>>>(xyz, points);

    // stage 3: DenseNet — 3xTF32 conv (k8 schedule) with fused BN-stat partials
    float* rawdst[4] = {Y + (size_t)CIN_*P_, Y + (size_t)(CIN_+HID_)*P_,
                        Y + (size_t)(CIN_+2*HID_)*P_, Xs};
    for (int l = 0; l < 4; l++){
        gemm_tc<<<dim3(NBLK_, COl[l]/128, 1), 256>>>(Wt + Woff[l], Y, rawdst[l],
                                                     prm, COl[l], P_, Kl[l]);
        bn_reduce<<<COl[l], 256>>>((l < 3) ? Kl[l] : -1, gl[l], bel[l]);
        if (l == 3)
            bn_relu_maxk<<<(B_*COUT_*S_)/256, 256>>>(Xs, gl[l], bel[l]);
    }

    // stage 5: dual attention
    long fS = (long)CS_;
    gemm_qk<<<dim3(S_/64, 1, 2*B_), 256>>>(Wq, Wk, bq, bk, feat, q, k);
    gemm_nn<<<dim3(S_/64, 4, B_), 256>>>(Wv, feat, v, bv, COUT_, S_, COUT_, 0, fS, fS);

    gemm_tn<<<dim3(S_/64, S_/64, B_), 256>>>(q, k, E, S_, S_, C8_, S_, S_,
                                             (long)C8_*S_, (long)C8_*S_, (long)S_*S_);
    softmax_rows_1024<<<B_*S_, 256>>>(E);
    gemm_tc2s<<<dim3(S_/128, COUT_/128, B_*4), 256>>>(v, E, opp,
                                                      COUT_, S_, 256, S_, S_, 1, 4,
                                                      fS, (long)S_*S_);

    // channel attention
    ec_kah_split<<<dim3(COUT_/64, COUT_/64, B_*4), 256>>>(feat, Ecp);
    softmax_c_kernel<<<B_*COUT_, 256>>>(Ecp, Ec);
    gemm_tc2s<<<dim3(S_/128, COUT_/128, B_*4), 256>>>(Ec, feat, ocp,
                                                      COUT_, S_, 64, COUT_, 0, 0, 4,
                                                      (long)COUT_*COUT_, fS);

    finalize_kernel<<<(B_*S_*COUT_)/256, 256>>>(out, gamma);
}